// round 4
// baseline (speedup 1.0000x reference)
#include <cuda_runtime.h>
#include <cuda_bf16.h>
#include <cstdint>

// Problem dims
#define BB   64
#define SS   512
#define NHH  4
#define DD   256
#define HH   256
#define MROWS (BB*SS*NHH)   // 131072

// ---------------- device scratch (static, allocation-free) ----------------
__device__ float g_kxW[(size_t)MROWS * 256];   // x @ (Wk@Wcomb)            (no bias)
__device__ float g_xW1[(size_t)MROWS * 256];   // x @ W1_top                (no bias)
__device__ float g_kscore[MROWS];
__device__ float g_Wcomb[256 * 256];           // Wproj @ W1_bot
__device__ float g_Wbig[256 * 512];            // [Wk@Wcomb | W1_top]  (K=256 rows, N=512)
__device__ float g_bias[512];                  // [bk@Wcomb | b1 + bproj@W1bot]
__device__ float g_vq[256];                    // Wq @ w2
__device__ float g_wk1[256];                   // Wk @ w1
__device__ float g_w2v[256];                   // W2 @ vq
__device__ float g_scalars[4];
__device__ float g_h1[BB * NHH * 256];
__device__ float g_hidden[BB * NHH * 256];
// bf16 split planes
__device__ __nv_bfloat16 g_Ahi[(size_t)MROWS * 256];   // [m][k] row-major
__device__ __nv_bfloat16 g_Alo[(size_t)MROWS * 256];
__device__ __nv_bfloat16 g_Bhi[512 * 256];             // [n][k] n-major (transposed)
__device__ __nv_bfloat16 g_Blo[512 * 256];

// ---------------- helpers ----------------
__device__ __forceinline__ uint32_t smem_u32(const void* p) {
    uint32_t a;
    asm("{ .reg .u64 t; cvta.to.shared.u64 t, %1; cvt.u32.u64 %0, t; }" : "=r"(a) : "l"(p));
    return a;
}
__device__ __forceinline__ void cpa16(void* s, const void* g) {
    uint32_t sa = smem_u32(s);
    asm volatile("cp.async.cg.shared.global [%0], [%1], 16;" :: "r"(sa), "l"(g));
}
__device__ __forceinline__ void cp16ca(float* s, const float* g) {
    uint32_t sa = smem_u32(s);
    asm volatile("cp.async.ca.shared.global [%0], [%1], 16;" :: "r"(sa), "l"(g));
}
#define LDSM4(r, addr) \
    asm volatile("ldmatrix.sync.aligned.m8n8.x4.shared.b16 {%0,%1,%2,%3}, [%4];" \
        : "=r"((r)[0]), "=r"((r)[1]), "=r"((r)[2]), "=r"((r)[3]) : "r"(addr))
#define MMA16816(d, a, b0, b1) \
    asm volatile("mma.sync.aligned.m16n8k16.row.col.f32.bf16.bf16.f32 " \
        "{%0,%1,%2,%3}, {%4,%5,%6,%7}, {%8,%9}, {%0,%1,%2,%3};" \
        : "+f"((d)[0]), "+f"((d)[1]), "+f"((d)[2]), "+f"((d)[3]) \
        : "r"((a)[0]), "r"((a)[1]), "r"((a)[2]), "r"((a)[3]), "r"(b0), "r"(b1))

// ---------------- small setup kernels ----------------
__global__ void k_setup1(const float* __restrict__ Wk, const float* __restrict__ bk,
                         const float* __restrict__ Wq, const float* __restrict__ bq,
                         const float* __restrict__ w_mlp) {
    __shared__ float sw1[256], sw2[256];
    int tid = threadIdx.x;
    sw1[tid] = w_mlp[tid];
    sw2[tid] = w_mlp[256 + tid];
    __syncthreads();
    float vq = 0.f, wk1 = 0.f;
    for (int h = 0; h < 256; h++) {
        vq  += Wq[tid * 256 + h] * sw2[h];
        wk1 += Wk[tid * 256 + h] * sw1[h];
    }
    g_vq[tid] = vq;
    g_wk1[tid] = wk1;
    if (tid == 0) {
        float cq = 0.f, ck1 = 0.f;
        for (int h = 0; h < 256; h++) { cq += bq[h] * sw2[h]; ck1 += bk[h] * sw1[h]; }
        g_scalars[0] = cq;
        g_scalars[1] = ck1;
    }
}

__global__ void k_wcomb(const float* __restrict__ Wproj, const float* __restrict__ W1) {
    __shared__ float sp[256];
    int h = blockIdx.x, tid = threadIdx.x;
    sp[tid] = Wproj[h * 256 + tid];
    __syncthreads();
    float acc = 0.f;
    for (int hp = 0; hp < 256; hp++)
        acc += sp[hp] * W1[(256 + hp) * 256 + tid];
    g_Wcomb[h * 256 + tid] = acc;
}

__global__ void k_wkc(const float* __restrict__ Wk, const float* __restrict__ W1,
                      const float* __restrict__ bk, const float* __restrict__ b1,
                      const float* __restrict__ bproj, const float* __restrict__ W2,
                      const float* __restrict__ b2) {
    int tid = threadIdx.x;
    if (blockIdx.x < 256) {
        int d = blockIdx.x;
        __shared__ float s[256];
        s[tid] = Wk[d * 256 + tid];
        __syncthreads();
        float acc = 0.f;
        for (int h = 0; h < 256; h++) acc += s[h] * g_Wcomb[h * 256 + tid];
        g_Wbig[d * 512 + tid]       = acc;
        g_Wbig[d * 512 + 256 + tid] = W1[d * 256 + tid];
    } else {
        float a = 0.f, bb = 0.f, w = 0.f;
        for (int h = 0; h < 256; h++) a  += bk[h]    * g_Wcomb[h * 256 + tid];
        for (int h = 0; h < 256; h++) bb += bproj[h] * W1[(256 + h) * 256 + tid];
        for (int h = 0; h < 256; h++) w  += W2[tid * 256 + h] * g_vq[h];
        g_bias[tid]       = a;
        g_bias[256 + tid] = b1[tid] + bb;
        g_w2v[tid] = w;
        if (tid == 0) {
            float c2 = 0.f;
            for (int h = 0; h < 256; h++) c2 += b2[h] * g_vq[h];
            g_scalars[2] = c2 + g_scalars[0];
        }
    }
}

// ---------------- conversion: x -> bf16 hi/lo planes (+ fused kscore) ----------
__global__ void __launch_bounds__(256) k_convA(const float* __restrict__ X) {
    int idx = blockIdx.x * 256 + threadIdx.x;
    size_t row = (size_t)idx >> 5;
    int q = idx & 31;
    const float* src = X + row * 256 + q * 8;
    float v[8];
    *(float4*)(v)     = *(const float4*)(src);
    *(float4*)(v + 4) = *(const float4*)(src + 4);
    float wkv[8];
    *(float4*)(wkv)     = *(const float4*)(g_wk1 + q * 8);
    *(float4*)(wkv + 4) = *(const float4*)(g_wk1 + q * 8 + 4);
    __nv_bfloat16 hi[8], lo[8];
    float dot = 0.f;
#pragma unroll
    for (int j = 0; j < 8; j++) {
        hi[j] = __float2bfloat16(v[j]);
        lo[j] = __float2bfloat16(v[j] - __bfloat162float(hi[j]));
        dot += v[j] * wkv[j];
    }
    *(uint4*)(g_Ahi + row * 256 + q * 8) = *(uint4*)hi;
    *(uint4*)(g_Alo + row * 256 + q * 8) = *(uint4*)lo;
#pragma unroll
    for (int off = 16; off; off >>= 1) dot += __shfl_down_sync(0xFFFFFFFFu, dot, off);
    if ((threadIdx.x & 31) == 0) g_kscore[row] = dot + g_scalars[1];
}

// Wbig [k][n=512] -> n-major planes [n][k=256]
__global__ void k_convBt() {
    int n = blockIdx.x, k = threadIdx.x;
    float w = g_Wbig[k * 512 + n];
    __nv_bfloat16 hi = __float2bfloat16(w);
    __nv_bfloat16 lo = __float2bfloat16(w - __bfloat162float(hi));
    g_Bhi[n * 256 + k] = hi;
    g_Blo[n * 256 + k] = lo;
}

// ---------------- mma.sync GEMM: C(131072x512) = X @ Wbig (split bf16, 3 products)
// CTA 64(M) x 128(N), 4 warps (warp tile 32x64), K chunks of 32, 3-stage cp.async.
// smem stage: A_hi 5120 | A_lo 5120 | B_hi 10240 | B_lo 10240  (rows padded to 40 bf16)
#define MSM_STAGE 30720
#define MSM_TOTAL (3 * MSM_STAGE)   // 92160

__global__ void __launch_bounds__(128) k_mma(int dummy) {
    extern __shared__ __align__(128) char smem[];
    const int nb = blockIdx.x;   // 0..3
    const int rb = blockIdx.y;   // 0..2047
    const int tid = threadIdx.x;
    const int wid = tid >> 5, lane = tid & 31;
    const int warp_m = wid & 1, warp_n = wid >> 1;
    const uint32_t sb = smem_u32(smem);

    float acc[2][8][4];
#pragma unroll
    for (int i = 0; i < 2; i++)
#pragma unroll
        for (int j = 0; j < 8; j++)
#pragma unroll
            for (int c = 0; c < 4; c++) acc[i][j][c] = 0.f;

    // ldmatrix lane addressing (row-padded stride 40 bf16 = 80B)
    const int lrow = lane & 15;
    const int lkb = (lane >> 4) * 16;   // byte offset of k-half
    uint32_t aoff[2], boff[4];
#pragma unroll
    for (int mt = 0; mt < 2; mt++)
        aoff[mt] = (uint32_t)((warp_m * 32 + mt * 16 + lrow) * 80 + lkb);
#pragma unroll
    for (int nt2 = 0; nt2 < 4; nt2++)
        boff[nt2] = (uint32_t)((warp_n * 64 + nt2 * 16 + lrow) * 80 + lkb);

    const int grow = tid >> 2, gpos = tid & 3;

    auto load_stage = [&](int kc, int buf) {
        char* base = smem + buf * MSM_STAGE;
#pragma unroll
        for (int i = 0; i < 2; i++) {
            int row = grow + i * 32;
            size_t g = ((size_t)(rb * 64 + row)) * 256 + kc * 32 + gpos * 8;
            int s = row * 80 + gpos * 16;
            cpa16(base + s,        g_Ahi + g);
            cpa16(base + 5120 + s, g_Alo + g);
        }
#pragma unroll
        for (int i = 0; i < 4; i++) {
            int row = grow + i * 32;
            size_t g = ((size_t)(nb * 128 + row)) * 256 + kc * 32 + gpos * 8;
            int s = row * 80 + gpos * 16;
            cpa16(base + 10240 + s, g_Bhi + g);
            cpa16(base + 20480 + s, g_Blo + g);
        }
    };

    load_stage(0, 0);
    asm volatile("cp.async.commit_group;" ::: "memory");
    load_stage(1, 1);
    asm volatile("cp.async.commit_group;" ::: "memory");

    int buf = 0;
#pragma unroll 1
    for (int kc = 0; kc < 8; kc++) {
        if (kc < 7) asm volatile("cp.async.wait_group 1;" ::: "memory");
        else        asm volatile("cp.async.wait_group 0;" ::: "memory");
        __syncthreads();
        if (kc + 2 < 8) {
            int nbuf = buf + 2; if (nbuf >= 3) nbuf -= 3;
            load_stage(kc + 2, nbuf);
            asm volatile("cp.async.commit_group;" ::: "memory");
        }
        const uint32_t sbuf = sb + buf * MSM_STAGE;
#pragma unroll
        for (int kh = 0; kh < 2; kh++) {
            const uint32_t kb = kh * 32;
            uint32_t bh[4][4], bl[4][4];
#pragma unroll
            for (int nt2 = 0; nt2 < 4; nt2++) {
                LDSM4(bh[nt2], sbuf + 10240 + boff[nt2] + kb);
                LDSM4(bl[nt2], sbuf + 20480 + boff[nt2] + kb);
            }
#pragma unroll
            for (int mt = 0; mt < 2; mt++) {
                uint32_t ah[4], al[4];
                LDSM4(ah, sbuf + aoff[mt] + kb);
                LDSM4(al, sbuf + 5120 + aoff[mt] + kb);
#pragma unroll
                for (int nt2 = 0; nt2 < 4; nt2++) {
                    MMA16816(acc[mt][2 * nt2],     ah, bh[nt2][0], bh[nt2][2]);
                    MMA16816(acc[mt][2 * nt2],     ah, bl[nt2][0], bl[nt2][2]);
                    MMA16816(acc[mt][2 * nt2],     al, bh[nt2][0], bh[nt2][2]);
                    MMA16816(acc[mt][2 * nt2 + 1], ah, bh[nt2][1], bh[nt2][3]);
                    MMA16816(acc[mt][2 * nt2 + 1], ah, bl[nt2][1], bl[nt2][3]);
                    MMA16816(acc[mt][2 * nt2 + 1], al, bh[nt2][1], bh[nt2][3]);
                }
            }
        }
        buf++; if (buf >= 3) buf -= 3;
    }

    // epilogue: stage to smem (padded 132) then coalesced float4 stores
    __syncthreads();
    float* sC = (float*)smem;
    {
        const int r0 = warp_m * 32 + (lane >> 2);
        const int c0 = warp_n * 64 + 2 * (lane & 3);
#pragma unroll
        for (int mt = 0; mt < 2; mt++) {
            int r = r0 + mt * 16;
#pragma unroll
            for (int nt = 0; nt < 8; nt++) {
                int c = c0 + nt * 8;
                sC[r * 132 + c]           = acc[mt][nt][0];
                sC[r * 132 + c + 1]       = acc[mt][nt][1];
                sC[(r + 8) * 132 + c]     = acc[mt][nt][2];
                sC[(r + 8) * 132 + c + 1] = acc[mt][nt][3];
            }
        }
    }
    __syncthreads();
    float* Cout = (nb < 2) ? g_kxW : g_xW1;
    const int colbase = (nb & 1) * 128;
#pragma unroll
    for (int i = tid; i < 2048; i += 128) {
        int row = i >> 5, c4 = i & 31;
        float4 v = *(float4*)&sC[row * 132 + c4 * 4];
        *(float4*)&Cout[((size_t)rb * 64 + row) * 256 + colbase + c4 * 4] = v;
    }
}

// ---------------- recurrent scan: one CTA per batch element, 4-stage pipeline ---
__global__ void __launch_bounds__(256) k_recurrent() {
    const int b = blockIdx.x;
    const int tid = threadIdx.x;
    const int lane = tid & 31, wid = tid >> 5;
    __shared__ __align__(16) float sk[4][1024];
    __shared__ __align__(16) float sx[4][1024];
    __shared__ __align__(16) float sks[4][4];
    __shared__ float qs[4];
    __shared__ float ps[16];
    __shared__ float wp[8][4];

    const float w2vh = g_w2v[tid];
    const float c2 = g_scalars[2];
    const float bk_ = g_bias[tid];
    const float bx_ = g_bias[256 + tid];
    if (tid < 4) qs[tid] = g_scalars[0];

#pragma unroll
    for (int s = 0; s < 4; s++) {
        size_t base = ((size_t)b * 512 + s) * 4 * 256;
        cp16ca(&sk[s][tid * 4], g_kxW + base + (size_t)tid * 4);
        cp16ca(&sx[s][tid * 4], g_xW1 + base + (size_t)tid * 4);
        if (tid == 0) cp16ca(sks[s], g_kscore + ((size_t)b * 512 + s) * 4);
        asm volatile("cp.async.commit_group;" ::: "memory");
    }
    __syncthreads();

    for (int t = 0; t < 512; t++) {
        const int buf = t & 3;
        asm volatile("cp.async.wait_group 3;" ::: "memory");
        __syncthreads();  // A: stage t ready + qs current

        if (tid < 16) {
            int i = tid >> 2;
            float s = tanhf(qs[i] + sks[buf][tid & 3]);
            float m = fmaxf(s, __shfl_xor_sync(0xFFFFu, s, 1));
            m = fmaxf(m, __shfl_xor_sync(0xFFFFu, m, 2));
            float e = __expf(s - m);
            float sum = e + __shfl_xor_sync(0xFFFFu, e, 1);
            sum += __shfl_xor_sync(0xFFFFu, sum, 2);
            ps[tid] = e / sum;
        }
        __syncthreads();  // B: ps visible

        const float k0 = sk[buf][tid] + bk_, k1 = sk[buf][256 + tid] + bk_,
                    k2 = sk[buf][512 + tid] + bk_, k3 = sk[buf][768 + tid] + bk_;
        float a0, a1, a2, a3;
        {
            float v = sx[buf][tid] + bx_ + ps[0] * k0 + ps[1] * k1 + ps[2] * k2 + ps[3] * k3;
            float h = fmaxf(v, 0.f);
            if (t == 511) g_h1[(b * 4 + 0) * 256 + tid] = h;
            a0 = h * w2vh;
        }
        {
            float v = sx[buf][256 + tid] + bx_ + ps[4] * k0 + ps[5] * k1 + ps[6] * k2 + ps[7] * k3;
            float h = fmaxf(v, 0.f);
            if (t == 511) g_h1[(b * 4 + 1) * 256 + tid] = h;
            a1 = h * w2vh;
        }
        {
            float v = sx[buf][512 + tid] + bx_ + ps[8] * k0 + ps[9] * k1 + ps[10] * k2 + ps[11] * k3;
            float h = fmaxf(v, 0.f);
            if (t == 511) g_h1[(b * 4 + 2) * 256 + tid] = h;
            a2 = h * w2vh;
        }
        {
            float v = sx[buf][768 + tid] + bx_ + ps[12] * k0 + ps[13] * k1 + ps[14] * k2 + ps[15] * k3;
            float h = fmaxf(v, 0.f);
            if (t == 511) g_h1[(b * 4 + 3) * 256 + tid] = h;
            a3 = h * w2vh;
        }
#pragma unroll
        for (int off = 16; off; off >>= 1) {
            a0 += __shfl_down_sync(0xFFFFFFFFu, a0, off);
            a1 += __shfl_down_sync(0xFFFFFFFFu, a1, off);
            a2 += __shfl_down_sync(0xFFFFFFFFu, a2, off);
            a3 += __shfl_down_sync(0xFFFFFFFFu, a3, off);
        }
        if (lane == 0) { wp[wid][0] = a0; wp[wid][1] = a1; wp[wid][2] = a2; wp[wid][3] = a3; }
        __syncthreads();  // C: wp visible, buf free

        if (t + 4 < 512) {
            size_t base = ((size_t)b * 512 + t + 4) * 4 * 256;
            cp16ca(&sk[buf][tid * 4], g_kxW + base + (size_t)tid * 4);
            cp16ca(&sx[buf][tid * 4], g_xW1 + base + (size_t)tid * 4);
            if (tid == 0) cp16ca(sks[buf], g_kscore + ((size_t)b * 512 + t + 4) * 4);
        }
        asm volatile("cp.async.commit_group;" ::: "memory");

        if (tid < 4) {
            float s = c2;
#pragma unroll
            for (int ww = 0; ww < 8; ww++) s += wp[ww][tid];
            qs[tid] = s;
        }
    }
}

// ---------------- epilogue ----------------
__global__ void k_hfinal(const float* __restrict__ W2, const float* __restrict__ b2,
                         float* __restrict__ out) {
    int r = blockIdx.x, tid = threadIdx.x;
    __shared__ float sh[256];
    sh[tid] = g_h1[r * 256 + tid];
    __syncthreads();
    float acc = b2[tid];
    for (int h = 0; h < 256; h++) acc += sh[h] * W2[h * 256 + tid];
    g_hidden[r * 256 + tid] = acc;
    out[192 + r * 256 + tid] = acc;
}

__global__ void k_logits(const float* __restrict__ Wo, const float* __restrict__ bo,
                         float* __restrict__ out) {
    int bidx = blockIdx.x, tid = threadIdx.x, lane = tid & 31, wid = tid >> 5;
    __shared__ float red[4][3];
    float p0 = 0.f, p1 = 0.f, p2 = 0.f;
    for (int k = tid; k < 1024; k += 128) {
        float h = g_hidden[bidx * 1024 + k];
        p0 += h * Wo[k * 3 + 0];
        p1 += h * Wo[k * 3 + 1];
        p2 += h * Wo[k * 3 + 2];
    }
#pragma unroll
    for (int off = 16; off; off >>= 1) {
        p0 += __shfl_down_sync(0xFFFFFFFFu, p0, off);
        p1 += __shfl_down_sync(0xFFFFFFFFu, p1, off);
        p2 += __shfl_down_sync(0xFFFFFFFFu, p2, off);
    }
    if (lane == 0) { red[wid][0] = p0; red[wid][1] = p1; red[wid][2] = p2; }
    __syncthreads();
    if (tid == 0) {
        float l0 = bo[0], l1 = bo[1], l2 = bo[2];
        for (int w = 0; w < 4; w++) { l0 += red[w][0]; l1 += red[w][1]; l2 += red[w][2]; }
        float m = fmaxf(l0, fmaxf(l1, l2));
        float lse = m + logf(expf(l0 - m) + expf(l1 - m) + expf(l2 - m));
        out[bidx * 3 + 0] = l0 - lse;
        out[bidx * 3 + 1] = l1 - lse;
        out[bidx * 3 + 2] = l2 - lse;
    }
}

// ---------------- launch ----------------
extern "C" void kernel_launch(void* const* d_in, const int* in_sizes, int n_in,
                              void* d_out, int out_size) {
    const float* x     = (const float*)d_in[0];
    const float* Wk    = (const float*)d_in[1];
    const float* bk    = (const float*)d_in[2];
    const float* Wq    = (const float*)d_in[3];
    const float* bq    = (const float*)d_in[4];
    const float* w_mlp = (const float*)d_in[5];
    const float* Wproj = (const float*)d_in[6];
    const float* bproj = (const float*)d_in[7];
    const float* W1    = (const float*)d_in[8];
    const float* b1    = (const float*)d_in[9];
    const float* W2    = (const float*)d_in[10];
    const float* b2    = (const float*)d_in[11];
    const float* Wo    = (const float*)d_in[12];
    const float* bo    = (const float*)d_in[13];
    float* out = (float*)d_out;

    static bool attr_done = false;
    if (!attr_done) {
        cudaFuncSetAttribute(k_mma, cudaFuncAttributeMaxDynamicSharedMemorySize, MSM_TOTAL);
        attr_done = true;
    }

    k_setup1<<<1, 256>>>(Wk, bk, Wq, bq, w_mlp);
    k_wcomb<<<256, 256>>>(Wproj, W1);
    k_wkc<<<257, 256>>>(Wk, W1, bk, b1, bproj, W2, b2);
    k_convA<<<16384, 256>>>(x);
    k_convBt<<<512, 256>>>();
    k_mma<<<dim3(4, 2048), 128, MSM_TOTAL>>>(0);
    k_recurrent<<<64, 256>>>();
    k_hfinal<<<256, 256>>>(W2, b2, out);
    k_logits<<<64, 128>>>(Wo, bo, out);
}

// round 5
// speedup vs baseline: 1.4817x; 1.4817x over previous
#include <cuda_runtime.h>
#include <cstdint>

// Problem dims
#define BB   64
#define SS   512
#define NHH  4
#define DD   256
#define HH   256
#define MROWS (BB*SS*NHH)   // 131072

// ---------------- device scratch (static, allocation-free) ----------------
__device__ float g_kxW[(size_t)MROWS * 256];   // x @ (Wk@Wcomb)   (no bias)
__device__ float g_xW1[(size_t)MROWS * 256];   // x @ W1_top       (no bias)
__device__ float g_kscore[MROWS];
__device__ float g_Wcomb[256 * 256];           // Wproj @ W1_bot
__device__ float g_Wbig[256 * 512];            // [Wk@Wcomb | W1_top]  (K=256 rows, N=512)
__device__ float g_bias[512];                  // [bk@Wcomb | b1 + bproj@W1bot]
__device__ float g_vq[256];                    // Wq @ w2
__device__ float g_wk1[256];                   // Wk @ w1
__device__ float g_w2v[256];                   // W2 @ vq
__device__ float g_scalars[4];                 // [cq, ck1, c2+cq]
__device__ float g_h1[BB * NHH * 256];
__device__ float g_hidden[BB * NHH * 256];

// ---------------- helpers ----------------
__device__ __forceinline__ uint32_t smem_u32(const void* p) {
    uint32_t a;
    asm("{ .reg .u64 t; cvta.to.shared.u64 t, %1; cvt.u32.u64 %0, t; }" : "=r"(a) : "l"(p));
    return a;
}
__device__ __forceinline__ void cpa16(void* s, const void* g) {
    uint32_t sa = smem_u32(s);
    asm volatile("cp.async.cg.shared.global [%0], [%1], 16;" :: "r"(sa), "l"(g));
}
// packed fp32x2 FMA (Blackwell): acc.{lo,hi} += a.{lo,hi} * b.{lo,hi}
#define FFMA2(acc, a, b) \
    asm("fma.rn.f32x2 %0, %1, %2, %0;" : "+l"(acc) : "l"(a), "l"(b))
__device__ __forceinline__ unsigned long long dup2(float x) {
    unsigned long long d;
    asm("mov.b64 %0, {%1, %1};" : "=l"(d) : "f"(x));
    return d;
}
__device__ __forceinline__ float lo32(unsigned long long v) { return __uint_as_float((unsigned)v); }
__device__ __forceinline__ float hi32(unsigned long long v) { return __uint_as_float((unsigned)(v >> 32)); }

// ---------------- small setup kernels ----------------
__global__ void k_setup1(const float* __restrict__ Wk, const float* __restrict__ bk,
                         const float* __restrict__ Wq, const float* __restrict__ bq,
                         const float* __restrict__ w_mlp) {
    __shared__ float sw1[256], sw2[256];
    int tid = threadIdx.x;
    sw1[tid] = w_mlp[tid];
    sw2[tid] = w_mlp[256 + tid];
    __syncthreads();
    float vq = 0.f, wk1 = 0.f;
    for (int h = 0; h < 256; h++) {
        vq  += Wq[tid * 256 + h] * sw2[h];
        wk1 += Wk[tid * 256 + h] * sw1[h];
    }
    g_vq[tid] = vq;
    g_wk1[tid] = wk1;
    if (tid == 0) {
        float cq = 0.f, ck1 = 0.f;
        for (int h = 0; h < 256; h++) { cq += bq[h] * sw2[h]; ck1 += bk[h] * sw1[h]; }
        g_scalars[0] = cq;
        g_scalars[1] = ck1;
    }
}

__global__ void k_wcomb(const float* __restrict__ Wproj, const float* __restrict__ W1) {
    __shared__ float sp[256];
    int h = blockIdx.x, tid = threadIdx.x;
    sp[tid] = Wproj[h * 256 + tid];
    __syncthreads();
    float acc = 0.f;
    for (int hp = 0; hp < 256; hp++)
        acc += sp[hp] * W1[(256 + hp) * 256 + tid];
    g_Wcomb[h * 256 + tid] = acc;
}

__global__ void k_wkc(const float* __restrict__ Wk, const float* __restrict__ W1,
                      const float* __restrict__ bk, const float* __restrict__ b1,
                      const float* __restrict__ bproj, const float* __restrict__ W2,
                      const float* __restrict__ b2) {
    int tid = threadIdx.x;
    if (blockIdx.x < 256) {
        int d = blockIdx.x;
        __shared__ float s[256];
        s[tid] = Wk[d * 256 + tid];
        __syncthreads();
        float acc = 0.f;
        for (int h = 0; h < 256; h++) acc += s[h] * g_Wcomb[h * 256 + tid];
        g_Wbig[d * 512 + tid]       = acc;
        g_Wbig[d * 512 + 256 + tid] = W1[d * 256 + tid];
    } else {
        float a = 0.f, bb = 0.f, w = 0.f;
        for (int h = 0; h < 256; h++) a  += bk[h]    * g_Wcomb[h * 256 + tid];
        for (int h = 0; h < 256; h++) bb += bproj[h] * W1[(256 + h) * 256 + tid];
        for (int h = 0; h < 256; h++) w  += W2[tid * 256 + h] * g_vq[h];
        g_bias[tid]       = a;
        g_bias[256 + tid] = b1[tid] + bb;
        g_w2v[tid] = w;
        if (tid == 0) {
            float c2 = 0.f;
            for (int h = 0; h < 256; h++) c2 += b2[h] * g_vq[h];
            g_scalars[2] = c2 + g_scalars[0];
        }
    }
}

// ---------------- GEMM v2: C(131072x512) = X(131072x256) @ g_Wbig(256x512)
// fp32 SIMT with packed f32x2 FMA. BM=128 BN=128 BK=8, 128 threads,
// thread tile TM=16 x TN=8 (N as two groups of 4: tx*4 and 64+tx*4).
__global__ void __launch_bounds__(128) k_gemm2(const float* __restrict__ A) {
    __shared__ float As[2][8][128];   // [k][m] transposed
    __shared__ float Bs[2][8][128];   // [k][n]
    const int nb = blockIdx.x;   // 0..3
    const int rb = blockIdx.y;   // 0..1023
    const int tid = threadIdx.x;
    const int tx = tid & 15, ty = tid >> 4;
    const float* Ab = A + (size_t)rb * 128 * 256 + (size_t)tid * 256;
    const float* Bb = g_Wbig + nb * 128;
    const int kRow = tid >> 4, colB = (tid & 15) * 8;

    unsigned long long acc[8][8];
#pragma unroll
    for (int i = 0; i < 8; i++)
#pragma unroll
        for (int j = 0; j < 8; j++) acc[i][j] = 0ull;

    float rA[8];

    auto ldgA = [&](int kc) {
        float4 u = *(const float4*)(Ab + kc * 8);
        float4 v = *(const float4*)(Ab + kc * 8 + 4);
        rA[0] = u.x; rA[1] = u.y; rA[2] = u.z; rA[3] = u.w;
        rA[4] = v.x; rA[5] = v.y; rA[6] = v.z; rA[7] = v.w;
    };
    auto stsA = [&](int buf) {
#pragma unroll
        for (int kk = 0; kk < 8; kk++) As[buf][kk][tid] = rA[kk];
    };
    auto cpB = [&](int kc, int buf) {
        const float* src = Bb + (size_t)(kc * 8 + kRow) * 512 + colB;
        cpa16(&Bs[buf][kRow][colB], src);
        cpa16(&Bs[buf][kRow][colB + 4], src + 4);
    };

    // prologue
    ldgA(0); stsA(0); cpB(0, 0);
    asm volatile("cp.async.commit_group;" ::: "memory");
    ldgA(1);

#pragma unroll 1
    for (int kc = 0; kc < 32; kc++) {
        const int buf = kc & 1;
        asm volatile("cp.async.wait_group 0;" ::: "memory");
        __syncthreads();
        if (kc + 1 < 32) {
            cpB(kc + 1, buf ^ 1);
            asm volatile("cp.async.commit_group;" ::: "memory");
            stsA(buf ^ 1);
        }
        if (kc + 2 < 32) ldgA(kc + 2);

#pragma unroll
        for (int k = 0; k < 8; k++) {
            const ulonglong2* pm = (const ulonglong2*)&As[buf][k][ty * 16];
            ulonglong2 m0 = pm[0], m1 = pm[1], m2 = pm[2], m3 = pm[3];
            unsigned long long a[8] = {m0.x, m0.y, m1.x, m1.y, m2.x, m2.y, m3.x, m3.y};
            float4 n0 = *(const float4*)&Bs[buf][k][tx * 4];
            float4 n1 = *(const float4*)&Bs[buf][k][64 + tx * 4];
            unsigned long long d[8];
            d[0] = dup2(n0.x); d[1] = dup2(n0.y); d[2] = dup2(n0.z); d[3] = dup2(n0.w);
            d[4] = dup2(n1.x); d[5] = dup2(n1.y); d[6] = dup2(n1.z); d[7] = dup2(n1.w);
#pragma unroll
            for (int mp = 0; mp < 8; mp++)
#pragma unroll
                for (int j = 0; j < 8; j++)
                    FFMA2(acc[mp][j], a[mp], d[j]);
        }
    }

    float* Cout = (nb < 2) ? g_kxW : g_xW1;
    const int colbase = (nb & 1) * 128;
#pragma unroll
    for (int mp = 0; mp < 8; mp++) {
        size_t r = (size_t)rb * 128 + ty * 16 + 2 * mp;
        float4 v;
        v.x = lo32(acc[mp][0]); v.y = lo32(acc[mp][1]); v.z = lo32(acc[mp][2]); v.w = lo32(acc[mp][3]);
        *(float4*)&Cout[r * 256 + colbase + tx * 4] = v;
        v.x = lo32(acc[mp][4]); v.y = lo32(acc[mp][5]); v.z = lo32(acc[mp][6]); v.w = lo32(acc[mp][7]);
        *(float4*)&Cout[r * 256 + colbase + 64 + tx * 4] = v;
        v.x = hi32(acc[mp][0]); v.y = hi32(acc[mp][1]); v.z = hi32(acc[mp][2]); v.w = hi32(acc[mp][3]);
        *(float4*)&Cout[(r + 1) * 256 + colbase + tx * 4] = v;
        v.x = hi32(acc[mp][4]); v.y = hi32(acc[mp][5]); v.z = hi32(acc[mp][6]); v.w = hi32(acc[mp][7]);
        *(float4*)&Cout[(r + 1) * 256 + colbase + 64 + tx * 4] = v;
    }
}

// ---------------- kscore GEMV: one warp per row ----------------
__global__ void k_kscore(const float* __restrict__ X) {
    int warp = threadIdx.x >> 5, lane = threadIdx.x & 31;
    size_t row = (size_t)blockIdx.x * 8 + warp;
    const float4* xp = reinterpret_cast<const float4*>(X + row * 256);
    const float4* wp = reinterpret_cast<const float4*>(g_wk1);
    float4 a = xp[lane], w = wp[lane];
    float d = a.x * w.x + a.y * w.y + a.z * w.z + a.w * w.w;
    float4 a2 = xp[lane + 32], w2 = wp[lane + 32];
    d += a2.x * w2.x + a2.y * w2.y + a2.z * w2.z + a2.w * w2.w;
#pragma unroll
    for (int off = 16; off; off >>= 1) d += __shfl_down_sync(0xFFFFFFFFu, d, off);
    if (lane == 0) g_kscore[row] = d + g_scalars[1];
}

// ---------------- recurrent scan v2: ONE WARP per (b, i) — no block syncs ------
// grid = 256 CTAs of 32 threads. cta = b*4 + i.
// smem ring: 4 stages x (kx 256 f4 | sx 64 f4 | ks 1 f4 | pad) = 4 x 324 f4.
__global__ void __launch_bounds__(32) k_recur2() {
    __shared__ __align__(16) float4 sbuf[4][324];
    const int cta = blockIdx.x;
    const int b = cta >> 2, i = cta & 3;
    const int lane = threadIdx.x;

    // per-lane constants: h indices {lane*4..+3} and {128+lane*4..+3}
    float4 wva = *(const float4*)(g_w2v + lane * 4);
    float4 wvb = *(const float4*)(g_w2v + 128 + lane * 4);
    float4 cba, cbb;
    {
        float4 bka = *(const float4*)(g_bias + lane * 4);
        float4 bkb = *(const float4*)(g_bias + 128 + lane * 4);
        float4 bxa = *(const float4*)(g_bias + 256 + lane * 4);
        float4 bxb = *(const float4*)(g_bias + 256 + 128 + lane * 4);
        cba.x = bka.x + bxa.x; cba.y = bka.y + bxa.y; cba.z = bka.z + bxa.z; cba.w = bka.w + bxa.w;
        cbb.x = bkb.x + bxb.x; cbb.y = bkb.y + bxb.y; cbb.z = bkb.z + bxb.z; cbb.w = bkb.w + bxb.w;
    }
    const float c2 = g_scalars[2];
    float qs = g_scalars[0];

    auto issue = [&](int t, int s) {
        const float4* kxg = (const float4*)(g_kxW + ((size_t)(b * 512 + t) * 4) * 256);
        const float4* sxg = (const float4*)(g_xW1 + ((size_t)((b * 512 + t) * 4 + i)) * 256);
        float4* st = sbuf[s];
#pragma unroll
        for (int u = 0; u < 8; u++) cpa16(&st[lane + u * 32], kxg + lane + u * 32);
        cpa16(&st[256 + lane * 2], sxg + lane * 2);
        cpa16(&st[256 + lane * 2 + 1], sxg + lane * 2 + 1);
        if (lane == 0) cpa16(&st[320], g_kscore + (size_t)(b * 512 + t) * 4);
        asm volatile("cp.async.commit_group;" ::: "memory");
    };

    issue(0, 0); issue(1, 1); issue(2, 2); issue(3, 3);

    for (int t = 0; t < 512; t++) {
        const int s = t & 3;
        asm volatile("cp.async.wait_group 3;" ::: "memory");
        __syncwarp();

        const float4* st = sbuf[s];
        // loads (independent of softmax — scheduler hoists them)
        float4 k0a = st[lane],        k0b = st[32 + lane];
        float4 k1a = st[64 + lane],   k1b = st[96 + lane];
        float4 k2a = st[128 + lane],  k2b = st[160 + lane];
        float4 k3a = st[192 + lane],  k3b = st[224 + lane];
        float4 sxa = st[256 + lane],  sxb = st[288 + lane];
        float4 ks4 = st[320];

        // 4-way softmax of tanh scores, computed redundantly in every lane
        float s0 = tanhf(qs + ks4.x), s1 = tanhf(qs + ks4.y);
        float s2 = tanhf(qs + ks4.z), s3 = tanhf(qs + ks4.w);
        float mx = fmaxf(fmaxf(s0, s1), fmaxf(s2, s3));
        float e0 = __expf(s0 - mx), e1 = __expf(s1 - mx);
        float e2 = __expf(s2 - mx), e3 = __expf(s3 - mx);
        float inv = 1.f / (e0 + e1 + e2 + e3);
        float p0 = e0 * inv, p1 = e1 * inv, p2 = e2 * inv, p3 = e3 * inv;

        float4 ra, rb;
        ra.x = fmaxf(sxa.x + cba.x + p0 * k0a.x + p1 * k1a.x + p2 * k2a.x + p3 * k3a.x, 0.f);
        ra.y = fmaxf(sxa.y + cba.y + p0 * k0a.y + p1 * k1a.y + p2 * k2a.y + p3 * k3a.y, 0.f);
        ra.z = fmaxf(sxa.z + cba.z + p0 * k0a.z + p1 * k1a.z + p2 * k2a.z + p3 * k3a.z, 0.f);
        ra.w = fmaxf(sxa.w + cba.w + p0 * k0a.w + p1 * k1a.w + p2 * k2a.w + p3 * k3a.w, 0.f);
        rb.x = fmaxf(sxb.x + cbb.x + p0 * k0b.x + p1 * k1b.x + p2 * k2b.x + p3 * k3b.x, 0.f);
        rb.y = fmaxf(sxb.y + cbb.y + p0 * k0b.y + p1 * k1b.y + p2 * k2b.y + p3 * k3b.y, 0.f);
        rb.z = fmaxf(sxb.z + cbb.z + p0 * k0b.z + p1 * k1b.z + p2 * k2b.z + p3 * k3b.z, 0.f);
        rb.w = fmaxf(sxb.w + cbb.w + p0 * k0b.w + p1 * k1b.w + p2 * k2b.w + p3 * k3b.w, 0.f);

        float dA = wva.x * ra.x + wva.y * ra.y + wva.z * ra.z + wva.w * ra.w;
        float dB = wvb.x * rb.x + wvb.y * rb.y + wvb.z * rb.z + wvb.w * rb.w;
        float dot = dA + dB;
#pragma unroll
        for (int off = 16; off; off >>= 1) dot += __shfl_xor_sync(0xFFFFFFFFu, dot, off);
        qs = c2 + dot;

        if (t == 511) {
            float* dst = g_h1 + (size_t)(b * 4 + i) * 256;
            *(float4*)(dst + lane * 4) = ra;
            *(float4*)(dst + 128 + lane * 4) = rb;
        }
        if (t + 4 < 512) issue(t + 4, s);
    }
}

// ---------------- epilogue ----------------
__global__ void k_hfinal(const float* __restrict__ W2, const float* __restrict__ b2,
                         float* __restrict__ out) {
    int r = blockIdx.x, tid = threadIdx.x;
    __shared__ float sh[256];
    sh[tid] = g_h1[r * 256 + tid];
    __syncthreads();
    float acc = b2[tid];
    for (int h = 0; h < 256; h++) acc += sh[h] * W2[h * 256 + tid];
    g_hidden[r * 256 + tid] = acc;
    out[192 + r * 256 + tid] = acc;
}

__global__ void k_logits(const float* __restrict__ Wo, const float* __restrict__ bo,
                         float* __restrict__ out) {
    int bidx = blockIdx.x, tid = threadIdx.x, lane = tid & 31, wid = tid >> 5;
    __shared__ float red[4][3];
    float p0 = 0.f, p1 = 0.f, p2 = 0.f;
    for (int k = tid; k < 1024; k += 128) {
        float h = g_hidden[bidx * 1024 + k];
        p0 += h * Wo[k * 3 + 0];
        p1 += h * Wo[k * 3 + 1];
        p2 += h * Wo[k * 3 + 2];
    }
#pragma unroll
    for (int off = 16; off; off >>= 1) {
        p0 += __shfl_down_sync(0xFFFFFFFFu, p0, off);
        p1 += __shfl_down_sync(0xFFFFFFFFu, p1, off);
        p2 += __shfl_down_sync(0xFFFFFFFFu, p2, off);
    }
    if (lane == 0) { red[wid][0] = p0; red[wid][1] = p1; red[wid][2] = p2; }
    __syncthreads();
    if (tid == 0) {
        float l0 = bo[0], l1 = bo[1], l2 = bo[2];
        for (int w = 0; w < 4; w++) { l0 += red[w][0]; l1 += red[w][1]; l2 += red[w][2]; }
        float m = fmaxf(l0, fmaxf(l1, l2));
        float lse = m + logf(expf(l0 - m) + expf(l1 - m) + expf(l2 - m));
        out[bidx * 3 + 0] = l0 - lse;
        out[bidx * 3 + 1] = l1 - lse;
        out[bidx * 3 + 2] = l2 - lse;
    }
}

// ---------------- launch ----------------
extern "C" void kernel_launch(void* const* d_in, const int* in_sizes, int n_in,
                              void* d_out, int out_size) {
    const float* x     = (const float*)d_in[0];
    const float* Wk    = (const float*)d_in[1];
    const float* bk    = (const float*)d_in[2];
    const float* Wq    = (const float*)d_in[3];
    const float* bq    = (const float*)d_in[4];
    const float* w_mlp = (const float*)d_in[5];
    const float* Wproj = (const float*)d_in[6];
    const float* bproj = (const float*)d_in[7];
    const float* W1    = (const float*)d_in[8];
    const float* b1    = (const float*)d_in[9];
    const float* W2    = (const float*)d_in[10];
    const float* b2    = (const float*)d_in[11];
    const float* Wo    = (const float*)d_in[12];
    const float* bo    = (const float*)d_in[13];
    float* out = (float*)d_out;

    k_setup1<<<1, 256>>>(Wk, bk, Wq, bq, w_mlp);
    k_wcomb<<<256, 256>>>(Wproj, W1);
    k_wkc<<<257, 256>>>(Wk, W1, bk, b1, bproj, W2, b2);
    k_gemm2<<<dim3(4, 1024), 128>>>(x);
    k_kscore<<<16384, 256>>>(x);
    k_recur2<<<256, 32>>>();
    k_hfinal<<<256, 256>>>(W2, b2, out);
    k_logits<<<64, 128>>>(Wo, bo, out);
}